// round 3
// baseline (speedup 1.0000x reference)
#include <cuda_runtime.h>
#include <cuda_bf16.h>

// Problem shapes (fixed by reference setup_inputs)
#define B    4
#define CIN  512
#define OUT  256
#define NN   4096

// Scratch (no cudaMalloc allowed)
__device__ float g_X[B * CIN];   // X[b,c] = sum_n x[b,c,n]
__device__ float g_E[B * OUT];   // E[b,o] = elu(sum_c W1[o,c]*X[b,c])

// ---------------------------------------------------------------------------
// Kernel 1: reduce x over N. One block per (b,c) row (16 KB each).
// 256 threads x 4 float4, loads FRONT-BATCHED for MLP=4 per thread.
// (measured ~4.1us = ~7.8 TB/s: at HBM roofline, do not touch)
// ---------------------------------------------------------------------------
__global__ __launch_bounds__(256) void k_rowsum(const float* __restrict__ x) {
    const int row = blockIdx.x;                 // 0 .. B*CIN-1
    const float4* __restrict__ p =
        reinterpret_cast<const float4*>(x + (size_t)row * NN);
    const int t = threadIdx.x;

    float4 v0 = p[t];
    float4 v1 = p[t + 256];
    float4 v2 = p[t + 512];
    float4 v3 = p[t + 768];

    float s0 = (v0.x + v0.y) + (v0.z + v0.w);
    float s1 = (v1.x + v1.y) + (v1.z + v1.w);
    float s2 = (v2.x + v2.y) + (v2.z + v2.w);
    float s3 = (v3.x + v3.y) + (v3.z + v3.w);
    float s  = (s0 + s1) + (s2 + s3);

    #pragma unroll
    for (int off = 16; off > 0; off >>= 1)
        s += __shfl_down_sync(0xffffffffu, s, off);

    __shared__ float sm[8];
    if ((t & 31) == 0) sm[t >> 5] = s;
    __syncthreads();
    if (t < 8) {
        float u = sm[t];
        #pragma unroll
        for (int off = 4; off > 0; off >>= 1)
            u += __shfl_down_sync(0xffu, u, off);
        if (t == 0) g_X[row] = u;
    }
}

// ---------------------------------------------------------------------------
// Kernel 2: tiny dot + elu. One block per o (256 blocks, 128 threads).
// Loads W1 row ONCE, computes all 4 batches' dots from it.
// ---------------------------------------------------------------------------
__global__ __launch_bounds__(128) void k_dot(const float* __restrict__ W1) {
    const int o = blockIdx.x;
    const int t = threadIdx.x;          // 0..127, each owns one float4 chunk
    const float4 w = reinterpret_cast<const float4*>(W1 + (size_t)o * CIN)[t];

    float s[B];
    #pragma unroll
    for (int b = 0; b < B; b++) {
        const float4 xv = reinterpret_cast<const float4*>(g_X + b * CIN)[t];
        s[b] = fmaf(w.x, xv.x, fmaf(w.y, xv.y, fmaf(w.z, xv.z, w.w * xv.w)));
    }
    #pragma unroll
    for (int off = 16; off > 0; off >>= 1) {
        #pragma unroll
        for (int b = 0; b < B; b++)
            s[b] += __shfl_down_sync(0xffffffffu, s[b], off);
    }
    __shared__ float sm[4][B];
    if ((t & 31) == 0) {
        #pragma unroll
        for (int b = 0; b < B; b++) sm[t >> 5][b] = s[b];
    }
    __syncthreads();
    if (t < B) {
        float u = sm[0][t] + sm[1][t] + sm[2][t] + sm[3][t];
        g_E[t * OUT + o] = (u > 0.f) ? u : expm1f(u);   // elu, alpha=1
    }
}

// ---------------------------------------------------------------------------
// Kernel 3: barrier-free broadcast. grid=2048 x 256 threads, 2 float4 each.
// E read is uniform per half-row, L2-hot.
// ---------------------------------------------------------------------------
__global__ __launch_bounds__(256) void k_broadcast(float* __restrict__ out) {
    const int i  = blockIdx.x * 512 + threadIdx.x;  // first float4 index
    const int bo = i >> 10;                         // 1024 float4 per row
    const float v = __ldg(&g_E[bo]);
    const float4 v4 = make_float4(v, v, v, v);
    float4* __restrict__ q = reinterpret_cast<float4*>(out);
    q[i]       = v4;
    q[i + 256] = v4;     // same row: (i%1024)+256 < 1024 since i%512 < 256... 
}

extern "C" void kernel_launch(void* const* d_in, const int* in_sizes, int n_in,
                              void* d_out, int out_size) {
    const float* x  = (const float*)d_in[0];   // [B, CIN, 1, NN]
    const float* W1 = (const float*)d_in[1];   // [OUT, CIN]
    // d_in[2] = w2, d_in[3] = bias_mat: unused (softmax over size-1 axis == 1)
    float* out = (float*)d_out;                // [B, OUT, 1, NN]

    k_rowsum<<<B * CIN, 256>>>(x);
    k_dot<<<OUT, 128>>>(W1);
    k_broadcast<<<(B * OUT * NN / 4) / 512, 256>>>(out);
}